// round 17
// baseline (speedup 1.0000x reference)
#include <cuda_runtime.h>
#include <cuda_bf16.h>
#include <math.h>

// Problem shapes (fixed by the dataset)
#define B_  4096
#define L_  200
#define D_  256
#define BN_EPS 1e-5f

// -------- scratch (no allocations allowed) --------
__device__ float g_pp[2 * B_ * D_];                     // 8 MB partial sums
__device__ __align__(16) unsigned int g_A[B_ * D_];     // 4 MB pooled, tf32
__device__ __align__(16) unsigned int g_Wt[D_ * D_];    // 256 KB W1, tf32
__device__ float g_z[B_ * D_];                          // 4 MB
__device__ float g_part[2 * 64 * D_];                   // stats partials
__device__ float g_lossp[256];
__device__ unsigned int g_ticket;
__device__ unsigned int g_syncc[2];

// float -> tf32 (round to nearest, bit pattern in u32)
__device__ __forceinline__ unsigned int f2tf32(float f)
{
    unsigned int u;
    asm("cvt.rna.tf32.f32 %0, %1;" : "=r"(u) : "f"(f));
    return u;
}

// emb load: non-coherent, L2 evict_last policy (keep table resident)
__device__ __forceinline__ float4 ldg_keep(const float4* p, unsigned long long pol)
{
    float4 v;
    asm volatile("ld.global.nc.L2::cache_hint.v4.f32 {%0,%1,%2,%3}, [%4], %5;"
                 : "=f"(v.x), "=f"(v.y), "=f"(v.z), "=f"(v.w)
                 : "l"(p), "l"(pol));
    return v;
}

#define CP_ASYNC16(dst_u32, src) \
    asm volatile("cp.async.cg.shared.global [%0], [%1], 16;" \
                 :: "r"(dst_u32), "l"(src))
#define CP_COMMIT() asm volatile("cp.async.commit_group;")
#define CP_WAIT1()  asm volatile("cp.async.wait_group 1;")
#define CP_WAIT0()  asm volatile("cp.async.wait_group 0;")

// ============================================================
// Kernel 1: ragged gather partial-pool (EXACT R8 best).
// 1 block = (row, token-half). 8192 blocks x 64 threads.
// ============================================================
__global__ void __launch_bounds__(64) pool_kernel(
    const int* __restrict__ tokens,
    const int* __restrict__ lengths,
    const float* __restrict__ emb)
{
    const int bid  = blockIdx.x;
    const int row  = bid >> 1;
    const int half = bid & 1;
    const int tid  = threadIdx.x;
    __shared__ int s_tok[104];

    unsigned long long pol;
    asm("createpolicy.fractional.L2::evict_last.b64 %0, 1.0;" : "=l"(pol));

    const int len   = lengths[row];
    const int n0    = len >> 1;
    const int start = half ? n0 : 0;
    const int cnt   = half ? (len - n0) : n0;

    for (int i = tid; i < cnt; i += 64)
        s_tok[i] = __ldcs(&tokens[row * L_ + start + i]);
    __syncthreads();

    const float4* __restrict__ emb4 = (const float4*)emb;  // row stride 64

    float4 a0 = make_float4(0.f, 0.f, 0.f, 0.f);
    float4 a1 = make_float4(0.f, 0.f, 0.f, 0.f);
    int l = 0;
    for (; l + 8 <= cnt; l += 8) {
        float4 v0 = ldg_keep(&emb4[(size_t)s_tok[l + 0] * 64 + tid], pol);
        float4 v1 = ldg_keep(&emb4[(size_t)s_tok[l + 1] * 64 + tid], pol);
        float4 v2 = ldg_keep(&emb4[(size_t)s_tok[l + 2] * 64 + tid], pol);
        float4 v3 = ldg_keep(&emb4[(size_t)s_tok[l + 3] * 64 + tid], pol);
        float4 v4 = ldg_keep(&emb4[(size_t)s_tok[l + 4] * 64 + tid], pol);
        float4 v5 = ldg_keep(&emb4[(size_t)s_tok[l + 5] * 64 + tid], pol);
        float4 v6 = ldg_keep(&emb4[(size_t)s_tok[l + 6] * 64 + tid], pol);
        float4 v7 = ldg_keep(&emb4[(size_t)s_tok[l + 7] * 64 + tid], pol);
        a0.x += (v0.x + v1.x) + (v2.x + v3.x);
        a0.y += (v0.y + v1.y) + (v2.y + v3.y);
        a0.z += (v0.z + v1.z) + (v2.z + v3.z);
        a0.w += (v0.w + v1.w) + (v2.w + v3.w);
        a1.x += (v4.x + v5.x) + (v6.x + v7.x);
        a1.y += (v4.y + v5.y) + (v6.y + v7.y);
        a1.z += (v4.z + v5.z) + (v6.z + v7.z);
        a1.w += (v4.w + v5.w) + (v6.w + v7.w);
    }
    for (; l < cnt; ++l) {
        float4 v = ldg_keep(&emb4[(size_t)s_tok[l] * 64 + tid], pol);
        a0.x += v.x; a0.y += v.y; a0.z += v.z; a0.w += v.w;
    }
    float4 o;
    o.x = a0.x + a1.x; o.y = a0.y + a1.y;
    o.z = a0.z + a1.z; o.w = a0.w + a1.w;
    __stcs(&((float4*)g_pp)[((size_t)half * B_ + row) * 64 + tid], o);
}

// ============================================================
// Kernel 1.5: combine pp halves -> /len -> tf32 g_A; W1 -> tf32.
// Blocks [0,512): A (each thread 2 float4). Blocks [512,576): W.
// ~16 MB of L2-speed traffic, full-grid parallel (~2 us).
// ============================================================
__global__ void __launch_bounds__(256) convert_kernel(
    const int* __restrict__ lengths,
    const float* __restrict__ W1)
{
    const int bid = blockIdx.x;
    const int tid = threadIdx.x;

    if (bid >= 512) {                       // ---- W converter ----
        int i = (bid - 512) * 256 + tid;    // float4 index, [0, 16384)
        float4 w = __ldg(&((const float4*)W1)[i]);
        uint4 o;
        o.x = f2tf32(w.x); o.y = f2tf32(w.y);
        o.z = f2tf32(w.z); o.w = f2tf32(w.w);
        ((uint4*)g_Wt)[i] = o;
        return;
    }

    const float4* __restrict__ pp4 = (const float4*)g_pp;
    #pragma unroll
    for (int rep = 0; rep < 2; ++rep) {
        int idx = bid * 256 + tid + rep * 131072;   // float4 idx, [0, 262144)
        int row = idx >> 6;
        float inv = 1.f / (float)lengths[row];
        float4 p0 = pp4[idx];
        float4 p1 = pp4[(size_t)B_ * 64 + idx];
        uint4 u;
        u.x = f2tf32((p0.x + p1.x) * inv);
        u.y = f2tf32((p0.y + p1.y) * inv);
        u.z = f2tf32((p0.z + p1.z) * inv);
        u.w = f2tf32((p0.w + p1.w) * inv);
        ((uint4*)g_A)[idx] = u;
    }
}

// ------------------------------------------------------------
// Monotonic grid barrier (R8-proven form); 256 blocks co-resident.
// ------------------------------------------------------------
#define NB 256
__device__ __forceinline__ void gsync(int idx)
{
    __syncthreads();
    __threadfence();
    if (threadIdx.x == 0) {
        unsigned int my     = atomicAdd(&g_syncc[idx], 1u);
        unsigned int target = (my / NB + 1u) * NB;
        while (atomicAdd(&g_syncc[idx], 0u) < target)
            __nanosleep(64);
        __threadfence();
    }
    __syncthreads();
}

// ============================================================
// Kernel 2 (fused, R13-proven): cp.async double-buffered tf32 GEMM
// + stats -> gsync -> head + ticketed loss.
// Dynamic smem: A0,W0,A1,W1 each [64][68] u32 = 69632 B.
// ============================================================
#define BUFW 68
#define BUFSZ (64 * BUFW)          // u32 per buffer

extern "C" __global__ void __launch_bounds__(256, 2) gemm_head_kernel(
    const float* __restrict__ b1,
    const float* __restrict__ gamma,
    const float* __restrict__ beta,
    const float* __restrict__ w2,
    const float* __restrict__ b2,
    const float* __restrict__ t,
    float* __restrict__ Z,
    float* __restrict__ out)
{
    extern __shared__ __align__(16) char dynsm[];
    unsigned int* bufs = (unsigned int*)dynsm;   // A0 W0 A1 W1

    const int tid  = threadIdx.x;
    const int lane = tid & 31;
    const int warp = tid >> 5;
    const int bid  = blockIdx.x;

    // =================== Phase A: tf32 GEMM + stats ======================
    {
        const int g  = lane >> 2;
        const int tq = lane & 3;
        const int wm = warp >> 1;
        const int wn = warp & 1;
        const int bm = (bid >> 2) * 64;
        const int bn = (bid & 3) * 64;

        const unsigned int smem_base =
            (unsigned int)__cvta_generic_to_shared(dynsm);
        const int m_  = tid >> 2;            // loader row 0..63
        const int k4_ = tid & 3;             // loader chunk col (x4 per j)

        auto fill = [&](int k0, int bsel) {
            const unsigned int abase =
                smem_base + (unsigned int)(bsel * 2 * BUFSZ) * 4u;
            const unsigned int wbase = abase + BUFSZ * 4u;
            #pragma unroll
            for (int j = 0; j < 4; ++j) {
                int k4 = j * 4 + k4_;
                unsigned int off = (unsigned int)(m_ * BUFW + k4 * 4) * 4u;
                CP_ASYNC16(abase + off,
                           &g_A[(size_t)(bm + m_) * D_ + k0 + k4 * 4]);
                CP_ASYNC16(wbase + off,
                           &g_Wt[(size_t)(bn + m_) * D_ + k0 + k4 * 4]);
            }
        };

        float c[4][4] = {};

        fill(0, 0);
        CP_COMMIT();

        #pragma unroll
        for (int k = 0; k < 4; ++k) {
            if (k < 3) { fill((k + 1) * 64, (k + 1) & 1); CP_COMMIT(); CP_WAIT1(); }
            else       { CP_WAIT0(); }
            __syncthreads();

            const unsigned int* As = bufs + (k & 1) * 2 * BUFSZ;
            const unsigned int* Bs = As + BUFSZ;
            const int am = wm * 16 + g;
            #pragma unroll
            for (int ks = 0; ks < 8; ++ks) {
                const int kc = ks * 8;
                unsigned int a0 = As[am * BUFW + kc + tq];
                unsigned int a1 = As[(am + 8) * BUFW + kc + tq];
                unsigned int a2 = As[am * BUFW + kc + tq + 4];
                unsigned int a3 = As[(am + 8) * BUFW + kc + tq + 4];
                #pragma unroll
                for (int nb = 0; nb < 4; ++nb) {
                    const int bnrow = wn * 32 + nb * 8 + g;
                    unsigned int b0  = Bs[bnrow * BUFW + kc + tq];
                    unsigned int b1r = Bs[bnrow * BUFW + kc + tq + 4];
                    asm volatile(
                        "mma.sync.aligned.m16n8k8.row.col.f32.tf32.tf32.f32 "
                        "{%0,%1,%2,%3}, {%4,%5,%6,%7}, {%8,%9}, {%0,%1,%2,%3};"
                        : "+f"(c[nb][0]), "+f"(c[nb][1]),
                          "+f"(c[nb][2]), "+f"(c[nb][3])
                        : "r"(a0), "r"(a1), "r"(a2), "r"(a3),
                          "r"(b0), "r"(b1r));
                }
            }
            __syncthreads();
        }

        // epilogue: bias + Z store + fused stats
        const int row0 = bm + wm * 16 + g;
        float colsum[8], colsq[8];

        #pragma unroll
        for (int nb = 0; nb < 4; ++nb) {
            const int col = bn + wn * 32 + nb * 8 + 2 * tq;
            const float bz0 = b1[col], bz1 = b1[col + 1];
            float v00 = c[nb][0] + bz0, v01 = c[nb][1] + bz1;
            float v10 = c[nb][2] + bz0, v11 = c[nb][3] + bz1;
            *(float2*)&Z[(size_t)row0 * D_ + col]       = make_float2(v00, v01);
            *(float2*)&Z[(size_t)(row0 + 8) * D_ + col] = make_float2(v10, v11);
            colsum[nb * 2 + 0] = v00 + v10;
            colsum[nb * 2 + 1] = v01 + v11;
            colsq [nb * 2 + 0] = fmaf(v00, v00, v10 * v10);
            colsq [nb * 2 + 1] = fmaf(v01, v01, v11 * v11);
        }

        float* rs  = (float*)bufs;                 // [32][65]
        float* rss = rs + 32 * 65;                 // [32][65]
        const int contrib = wm * 8 + g;
        #pragma unroll
        for (int nb = 0; nb < 4; ++nb) {
            #pragma unroll
            for (int j = 0; j < 2; ++j) {
                int col = wn * 32 + nb * 8 + 2 * tq + j;
                rs [contrib * 65 + col] = colsum[nb * 2 + j];
                rss[contrib * 65 + col] = colsq [nb * 2 + j];
            }
        }
        __syncthreads();
        if (tid < 64) {
            float s = 0.f, ssq = 0.f;
            #pragma unroll 8
            for (int i = 0; i < 32; ++i) {
                s   += rs [i * 65 + tid];
                ssq += rss[i * 65 + tid];
            }
            g_part[(bid >> 2) * D_ + bn + tid]           = s;
            g_part[64 * D_ + (bid >> 2) * D_ + bn + tid] = ssq;
        }
    }

    gsync(0);

    // =================== Phase B: head (16 rows/block) ===================
    {
        float* s_g  = (float*)dynsm;
        float* s_be = s_g + D_;
        float* s_w  = s_be + D_;
        float* red  = s_w + D_;                    // 8 floats

        float smv = 0.f, sq = 0.f;
        #pragma unroll 16
        for (int rb = 0; rb < 64; ++rb) {
            smv += g_part[rb * D_ + tid];
            sq  += g_part[64 * D_ + rb * D_ + tid];
        }
        float mu   = smv * (1.f / (float)B_);
        float var  = sq  * (1.f / (float)B_) - mu * mu;
        float rstd = rsqrtf(var + BN_EPS);
        float gg   = gamma[tid] * rstd;
        s_g[tid]  = gg;
        s_be[tid] = beta[tid] - gg * mu;
        s_w[tid]  = w2[tid];
        __syncthreads();

        const int row0 = bid * 16 + warp * 2;
        const float b2v = b2[0];

        float acc[2] = {0.f, 0.f};
        #pragma unroll
        for (int k = 0; k < 8; ++k) {
            int dm = lane + 32 * k;
            float gk = s_g[dm], bek = s_be[dm], wk = s_w[dm];
            #pragma unroll
            for (int r = 0; r < 2; ++r) {
                float zv = Z[(size_t)(row0 + r) * D_ + dm];
                acc[r] += fmaxf(fmaf(gk, zv, bek), 0.f) * wk;
            }
        }
        #pragma unroll
        for (int off = 16; off > 0; off >>= 1) {
            acc[0] += __shfl_xor_sync(0xFFFFFFFFu, acc[0], off);
            acc[1] += __shfl_xor_sync(0xFFFFFFFFu, acc[1], off);
        }

        if (lane == 0) {
            float lossacc = 0.f;
            #pragma unroll
            for (int r = 0; r < 2; ++r) {
                float l = acc[r] + b2v;
                out[1 + row0 + r] = l;
                float tb = t[row0 + r];
                lossacc += fmaxf(l, 0.f) - l * tb + log1pf(expf(-fabsf(l)));
            }
            red[warp] = lossacc;
        }
        __syncthreads();

        __shared__ int s_last;
        if (tid == 0) {
            float sum = 0.f;
            #pragma unroll
            for (int w = 0; w < 8; ++w) sum += red[w];
            g_lossp[bid] = sum;
            __threadfence();
            unsigned int my = atomicAdd(&g_ticket, 1u);
            s_last = ((my + 1u) & 255u) == 0u;
        }
        __syncthreads();

        if (s_last) {
            __threadfence();
            if (warp == 0) {
                float v = 0.f;
                #pragma unroll
                for (int j = 0; j < 8; ++j)
                    v += g_lossp[lane + 32 * j];
                #pragma unroll
                for (int off = 16; off > 0; off >>= 1)
                    v += __shfl_xor_sync(0xFFFFFFFFu, v, off);
                if (lane == 0) out[0] = v * (1.f / (float)B_);
            }
        }
    }
}

// ============================================================
// launch: 3 kernels, serial
// ============================================================
extern "C" void kernel_launch(void* const* d_in, const int* in_sizes, int n_in,
                              void* d_out, int out_size)
{
    const int*   tokens  = (const int*)d_in[0];
    const int*   lengths = (const int*)d_in[1];
    const float* t       = (const float*)d_in[2];
    const float* emb     = (const float*)d_in[3];
    const float* W1      = (const float*)d_in[4];
    const float* b1      = (const float*)d_in[5];
    const float* gamma   = (const float*)d_in[6];
    const float* beta    = (const float*)d_in[7];
    const float* w2      = (const float*)d_in[8];
    const float* b2      = (const float*)d_in[9];
    float* out = (float*)d_out;

    float* z; cudaGetSymbolAddress((void**)&z, g_z);

    const int dyn_smem = 4 * BUFSZ * 4;   // 69632 B
    cudaFuncSetAttribute(gemm_head_kernel,
                         cudaFuncAttributeMaxDynamicSharedMemorySize, dyn_smem);

    pool_kernel<<<B_ * 2, 64>>>(tokens, lengths, emb);

    convert_kernel<<<576, 256>>>(lengths, W1);

    gemm_head_kernel<<<NB, 256, dyn_smem>>>(b1, gamma, beta, w2, b2, t,
                                            z, out);
}